// round 4
// baseline (speedup 1.0000x reference)
#include <cuda_runtime.h>
#include <math.h>

// Problem constants (fixed by reference setup_inputs)
#define BATCH 64
#define NPTS  16384
#define DIM   16
#define GRID  128                       // 2 blocks per batch, single wave
#define T1    256
#define NPAIR 72                        // packed f32x2 triangle entries
#define NPACKF (NPAIR * 2)              // 144 floats incl junk slots
#define ROWS_PER_BLOCK (NPTS / 2)       // 8192
#define ROWS_PER_WARP  (ROWS_PER_BLOCK / 8)  // 1024
#define ITERS (ROWS_PER_WARP / 32)      // 32 iterations x 32 rows per warp
#define NTERMS 9                        // Mercator terms, ||E||~0.065 -> err ~1e-12

__device__ float g_scratch[GRID * NPACKF];
__device__ unsigned int g_arrive;       // monotonic across graph replays

#define PACK2(d, lo, hi) \
    asm("mov.b64 %0, {%1, %2};" : "=l"(d) : "f"(lo), "f"(hi))
#define FMA2(d, a, b) \
    asm("fma.rn.f32x2 %0, %1, %2, %0;" : "+l"(d) : "l"(a), "l"(b))
#define ADD2(d, a, b) \
    asm("add.rn.f32x2 %0, %1, %2;" : "=l"(d) : "l"(a), "l"(b))

__device__ __forceinline__ unsigned int ld_acq(const unsigned int* p) {
    unsigned int v;
    asm volatile("ld.acquire.gpu.u32 %0, [%1];" : "=r"(v) : "l"(p));
    return v;
}

__device__ __forceinline__ float4 shfl_xor_f4(float4 v, int d) {
    float4 r;
    r.x = __shfl_xor_sync(0xFFFFFFFFu, v.x, d);
    r.y = __shfl_xor_sync(0xFFFFFFFFu, v.y, d);
    r.z = __shfl_xor_sync(0xFFFFFFFFu, v.z, d);
    r.w = __shfl_xor_sync(0xFFFFFFFFu, v.w, d);
    return r;
}

// ---------------------------------------------------------------------------
// Fused kernel.
// Phase 1: per-(batch,half) second-moment triangle. Coalesced LDG.128 +
//   quad shfl_xor row assembly (no SMEM transpose), f32x2 packed FMAs.
// Grid spin barrier (monotonic ticket).
// Phase 2 (blocks 0..63): logm Mercator series + signed power + FC + L2 norm.
// ---------------------------------------------------------------------------
__global__ __launch_bounds__(T1, 1) void soap_fused(
    const float* __restrict__ x, const float* __restrict__ W,
    const float* __restrict__ bias, const float* __restrict__ p,
    float* __restrict__ out) {

    __shared__ unsigned long long red[8][NPAIR];        // 4.6 KB
    __shared__ float Em[16][17];
    __shared__ float Pm[2][16][17];
    __shared__ float mf[256];
    __shared__ float fvv[256];
    __shared__ float warpsum[8];
    __shared__ float s_nrm;

    const int tid = threadIdx.x;
    const int w = tid >> 5;
    const int l = tid & 31;
    const int q = l & 3;                // quad position
    const int blk = blockIdx.x;
    const int b = blk >> 1;
    const int s = blk & 1;

    // ---------------- Phase 1: cov partial -------------------------------
    // Warp w handles rows [w*1024, (w+1)*1024) of this block's 8192-row half.
    const float4* __restrict__ src = (const float4*)x +
        ((size_t)b * NPTS + (size_t)s * ROWS_PER_BLOCK + (size_t)w * ROWS_PER_WARP) * 4
        + l;

    unsigned long long acc[NPAIR];
#pragma unroll
    for (int c = 0; c < NPAIR; c++) acc[c] = 0ull;

#pragma unroll 2
    for (int it = 0; it < ITERS; ++it) {
        // coalesced: lane l loads element indices it*128 + 32k + l
        float4 reg[4];
        const float4* sp = src + it * 128;
#pragma unroll
        for (int k = 0; k < 4; k++) reg[k] = sp[32 * k];

        // Quad exchange: lane (4m+q) ends up owning full row 8q+m.
        // Quarter p of my row: p==q -> reg[q]; p==q^d -> shfl_xor(reg[q^d], d).
        float4 quart[4];
        quart[q] = reg[q];
#pragma unroll
        for (int d = 1; d < 4; d++) {
            // send reg[q^d]; receive partner's reg[q] = quarter (q^d) of my row
            float4 rv = shfl_xor_f4(reg[q ^ d], d);
            quart[q ^ d] = rv;
        }

        float xv[16];
#pragma unroll
        for (int pq = 0; pq < 4; pq++) {
            xv[pq * 4 + 0] = quart[pq].x;
            xv[pq * 4 + 1] = quart[pq].y;
            xv[pq * 4 + 2] = quart[pq].z;
            xv[pq * 4 + 3] = quart[pq].w;
        }

        unsigned long long xp[8];
#pragma unroll
        for (int k = 0; k < 8; k++) PACK2(xp[k], xv[2 * k], xv[2 * k + 1]);

        int bcnt = 0;
#pragma unroll
        for (int i = 0; i < 16; i++) {
            unsigned long long bc;
            PACK2(bc, xv[i], xv[i]);
            const int np = (i + 2) >> 1;
#pragma unroll
            for (int jp = 0; jp < np; jp++) FMA2(acc[bcnt + jp], bc, xp[jp]);
            bcnt += np;
        }
    }

    // butterfly reduce within warp (packed adds), then cross-warp via shared
#pragma unroll
    for (int c = 0; c < NPAIR; c++) {
        unsigned long long v = acc[c];
#pragma unroll
        for (int off = 16; off >= 1; off >>= 1) {
            unsigned long long o = __shfl_xor_sync(0xFFFFFFFFu, v, off);
            ADD2(v, v, o);
        }
        if (l == 0) red[w][c] = v;
    }
    __syncthreads();

    if (tid < NPACKF) {
        const float* redf = (const float*)red;
        float v = 0.f;
#pragma unroll
        for (int ww = 0; ww < 8; ww++) v += redf[ww * NPACKF + tid];
        g_scratch[blk * NPACKF + tid] = v;
    }
    __threadfence();
    __syncthreads();

    // ---------------- Grid spin barrier (monotonic ticket) ----------------
    if (tid == 0) {
        const unsigned int t = atomicAdd(&g_arrive, 1u);
        const unsigned int target = (t / GRID + 1u) * GRID;
        while (ld_acq(&g_arrive) < target) __nanosleep(32);
    }
    __syncthreads();

    // ---------------- Phase 2: finish (blocks 0..63) -----------------------
    if (blk >= BATCH) return;
    const int b2 = blk;

    // Assemble E = cov/N - I from the two half partials (packed layout).
    if (tid < 136) {
        int c = tid, i = 0;
        while (c >= i + 1) { c -= i + 1; i++; }
        const int j = c;
        int bs = 0;
#pragma unroll
        for (int r = 0; r < 16; r++) if (r < i) bs += (r + 2) >> 1;
        const int fidx = (bs + (j >> 1)) * 2 + (j & 1);
        float v = g_scratch[(b2 * 2 + 0) * NPACKF + fidx] +
                  g_scratch[(b2 * 2 + 1) * NPACKF + fidx];
        v *= (1.0f / (float)NPTS);
        const float e = v - (i == j ? 1.0f : 0.0f);
        Em[i][j] = e;
        Em[j][i] = e;
    }
    __syncthreads();

    const int i = (tid >> 4) & 15;
    const int j = tid & 15;
    const float e0 = Em[i][j];
    Pm[0][i][j] = e0;
    float macc = e0;
    __syncthreads();

    int cur = 0;
#pragma unroll
    for (int k = 2; k <= NTERMS; k++) {
        float a = 0.f;
#pragma unroll
        for (int ll = 0; ll < 16; ll++) a = fmaf(Pm[cur][i][ll], Em[ll][j], a);
        Pm[cur ^ 1][i][j] = a;
        const float coef = ((k & 1) ? 1.0f : -1.0f) / (float)k;
        macc = fmaf(coef, a, macc);
        cur ^= 1;
        __syncthreads();
    }

    // signed power normalization
    {
        const float pe = p[0];
        const float sgn = (macc > 0.f) ? 1.0f : ((macc < 0.f) ? -1.0f : 0.0f);
        mf[tid] = sgn * powf(fabsf(macc), pe);
    }
    __syncthreads();

    // FC: one thread per output row; two accumulators for ILP
    {
        const float4* __restrict__ Wr = (const float4*)(W + (size_t)tid * 256);
        const float4* __restrict__ mv = (const float4*)mf;
        float a0 = 0.f, a1 = 0.f;
#pragma unroll
        for (int k4 = 0; k4 < 64; k4 += 2) {
            const float4 w0 = Wr[k4],     m0 = mv[k4];
            const float4 w1 = Wr[k4 + 1], m1 = mv[k4 + 1];
            a0 = fmaf(w0.x, m0.x, a0); a0 = fmaf(w0.y, m0.y, a0);
            a0 = fmaf(w0.z, m0.z, a0); a0 = fmaf(w0.w, m0.w, a0);
            a1 = fmaf(w1.x, m1.x, a1); a1 = fmaf(w1.y, m1.y, a1);
            a1 = fmaf(w1.z, m1.z, a1); a1 = fmaf(w1.w, m1.w, a1);
        }
        fvv[tid] = a0 + a1 + bias[tid];
    }
    __syncthreads();

    // L2 normalize
    {
        float sq = fvv[tid] * fvv[tid];
        sq += __shfl_xor_sync(0xFFFFFFFFu, sq, 16);
        sq += __shfl_xor_sync(0xFFFFFFFFu, sq, 8);
        sq += __shfl_xor_sync(0xFFFFFFFFu, sq, 4);
        sq += __shfl_xor_sync(0xFFFFFFFFu, sq, 2);
        sq += __shfl_xor_sync(0xFFFFFFFFu, sq, 1);
        if (l == 0) warpsum[w] = sq;
    }
    __syncthreads();
    if (tid == 0) {
        float ss = 0.f;
#pragma unroll
        for (int ww = 0; ww < 8; ww++) ss += warpsum[ww];
        s_nrm = fmaxf(sqrtf(ss), 1e-12f);
    }
    __syncthreads();
    out[(size_t)b2 * 256 + tid] = fvv[tid] / s_nrm;
}

// ---------------------------------------------------------------------------
// kernel_launch: x [64*16384*16] f32, W [256*256] f32, b [256] f32, p [1] f32.
// out: [64*256] f32.
// ---------------------------------------------------------------------------
extern "C" void kernel_launch(void* const* d_in, const int* in_sizes, int n_in,
                              void* d_out, int out_size) {
    const float* x    = (const float*)d_in[0];
    const float* W    = (const float*)d_in[1];
    const float* bias = (const float*)d_in[2];
    const float* p    = (const float*)d_in[3];
    float* out = (float*)d_out;

    soap_fused<<<GRID, T1>>>(x, W, bias, p, out);
}

// round 5
// speedup vs baseline: 2.5750x; 2.5750x over previous
#include <cuda_runtime.h>
#include <math.h>

// Problem constants (fixed by reference setup_inputs)
#define BATCH 64
#define NPTS  16384
#define DIM   16
#define GRID  128                       // 2 blocks per batch, single wave
#define T1    256
#define NPAIR 72                        // packed f32x2 triangle entries
#define NPACKF (NPAIR * 2)              // 144 floats incl junk slots
#define ROWS_PER_BLOCK (NPTS / 2)       // 8192
#define ITERS (ROWS_PER_BLOCK / T1)     // 32 rows per thread
#define NTERMS 9                        // Mercator terms, ||E||~0.065 -> err ~1e-12

__device__ float g_scratch[GRID * NPACKF];
__device__ unsigned int g_arrive;       // monotonic across graph replays

#define PACK2(d, lo, hi) \
    asm("mov.b64 %0, {%1, %2};" : "=l"(d) : "f"(lo), "f"(hi))
#define FMA2(d, a, b) \
    asm("fma.rn.f32x2 %0, %1, %2, %0;" : "+l"(d) : "l"(a), "l"(b))
#define ADD2(d, a, b) \
    asm("add.rn.f32x2 %0, %1, %2;" : "=l"(d) : "l"(a), "l"(b))

__device__ __forceinline__ unsigned int ld_acq(const unsigned int* p) {
    unsigned int v;
    asm volatile("ld.acquire.gpu.u32 %0, [%1];" : "=r"(v) : "l"(p));
    return v;
}

// ---------------------------------------------------------------------------
// Fused kernel.
// Phase 1: per-(batch,half) second-moment triangle. Direct strided LDG.128
//   (each thread owns whole rows -> all register indices STATIC), double-
//   buffered software pipeline, f32x2 packed FMAs.
// Grid spin barrier (monotonic ticket; GRID=128 <= 148 SMs so all resident).
// Phase 2 (blocks 0..63): logm Mercator series + signed power + FC + L2 norm.
// ---------------------------------------------------------------------------
__global__ __launch_bounds__(T1, 1) void soap_fused(
    const float* __restrict__ x, const float* __restrict__ W,
    const float* __restrict__ bias, const float* __restrict__ p,
    float* __restrict__ out) {

    __shared__ unsigned long long red[8][NPAIR];        // 4.6 KB
    __shared__ float Em[16][17];
    __shared__ float Pm[2][16][17];
    __shared__ float mf[256];
    __shared__ float fvv[256];
    __shared__ float warpsum[8];
    __shared__ float s_nrm;

    const int tid = threadIdx.x;
    const int w = tid >> 5;
    const int l = tid & 31;
    const int blk = blockIdx.x;
    const int b = blk >> 1;
    const int s = blk & 1;

    // ---------------- Phase 1: cov partial -------------------------------
    // Thread handles rows {it*256 + tid : it in [0,32)} of its 8192-row half.
    const float4* __restrict__ xb =
        (const float4*)(x + ((size_t)b * NPTS + (size_t)s * ROWS_PER_BLOCK) * DIM);

    unsigned long long acc[NPAIR];
#pragma unroll
    for (int c = 0; c < NPAIR; c++) acc[c] = 0ull;

    float4 buf[2][4];
    {
        const float4* sp = xb + (size_t)tid * 4;
#pragma unroll
        for (int k = 0; k < 4; k++) buf[0][k] = sp[k];
    }

#pragma unroll 2
    for (int it = 0; it < ITERS; ++it) {
        // prefetch next row while computing current (double buffer, static idx)
        if (it + 1 < ITERS) {
            const float4* sp = xb + ((size_t)(it + 1) * T1 + tid) * 4;
#pragma unroll
            for (int k = 0; k < 4; k++) buf[(it + 1) & 1][k] = sp[k];
        }

        const float4 v0 = buf[it & 1][0];
        const float4 v1 = buf[it & 1][1];
        const float4 v2 = buf[it & 1][2];
        const float4 v3 = buf[it & 1][3];
        float xv[16];
        xv[0]=v0.x; xv[1]=v0.y; xv[2]=v0.z; xv[3]=v0.w;
        xv[4]=v1.x; xv[5]=v1.y; xv[6]=v1.z; xv[7]=v1.w;
        xv[8]=v2.x; xv[9]=v2.y; xv[10]=v2.z; xv[11]=v2.w;
        xv[12]=v3.x; xv[13]=v3.y; xv[14]=v3.z; xv[15]=v3.w;

        unsigned long long xp[8];
#pragma unroll
        for (int k = 0; k < 8; k++) PACK2(xp[k], xv[2 * k], xv[2 * k + 1]);

        int bcnt = 0;
#pragma unroll
        for (int i = 0; i < 16; i++) {
            unsigned long long bc;
            PACK2(bc, xv[i], xv[i]);
            const int np = (i + 2) >> 1;
#pragma unroll
            for (int jp = 0; jp < np; jp++) FMA2(acc[bcnt + jp], bc, xp[jp]);
            bcnt += np;
        }
    }

    // butterfly reduce within warp (packed adds), then cross-warp via shared
#pragma unroll
    for (int c = 0; c < NPAIR; c++) {
        unsigned long long v = acc[c];
#pragma unroll
        for (int off = 16; off >= 1; off >>= 1) {
            unsigned long long o = __shfl_xor_sync(0xFFFFFFFFu, v, off);
            ADD2(v, v, o);
        }
        if (l == 0) red[w][c] = v;
    }
    __syncthreads();

    if (tid < NPACKF) {
        const float* redf = (const float*)red;
        float v = 0.f;
#pragma unroll
        for (int ww = 0; ww < 8; ww++) v += redf[ww * NPACKF + tid];
        g_scratch[blk * NPACKF + tid] = v;
    }
    __threadfence();
    __syncthreads();

    // ---------------- Grid spin barrier (monotonic ticket) ----------------
    if (tid == 0) {
        const unsigned int t = atomicAdd(&g_arrive, 1u);
        const unsigned int target = (t / GRID + 1u) * GRID;
        while (ld_acq(&g_arrive) < target) __nanosleep(32);
    }
    __syncthreads();

    // ---------------- Phase 2: finish (blocks 0..63) -----------------------
    if (blk >= BATCH) return;
    const int b2 = blk;

    // Assemble E = cov/N - I from the two half partials (packed layout).
    if (tid < 136) {
        int c = tid, i = 0;
        while (c >= i + 1) { c -= i + 1; i++; }
        const int j = c;
        int bs = 0;
#pragma unroll
        for (int r = 0; r < 16; r++) if (r < i) bs += (r + 2) >> 1;
        const int fidx = (bs + (j >> 1)) * 2 + (j & 1);
        float v = g_scratch[(b2 * 2 + 0) * NPACKF + fidx] +
                  g_scratch[(b2 * 2 + 1) * NPACKF + fidx];
        v *= (1.0f / (float)NPTS);
        const float e = v - (i == j ? 1.0f : 0.0f);
        Em[i][j] = e;
        Em[j][i] = e;
    }
    __syncthreads();

    const int i = (tid >> 4) & 15;
    const int j = tid & 15;
    const float e0 = Em[i][j];
    Pm[0][i][j] = e0;
    float macc = e0;
    __syncthreads();

    int cur = 0;
#pragma unroll
    for (int k = 2; k <= NTERMS; k++) {
        float a = 0.f;
#pragma unroll
        for (int ll = 0; ll < 16; ll++) a = fmaf(Pm[cur][i][ll], Em[ll][j], a);
        Pm[cur ^ 1][i][j] = a;
        const float coef = ((k & 1) ? 1.0f : -1.0f) / (float)k;
        macc = fmaf(coef, a, macc);
        cur ^= 1;
        __syncthreads();
    }

    // signed power normalization
    {
        const float pe = p[0];
        const float sgn = (macc > 0.f) ? 1.0f : ((macc < 0.f) ? -1.0f : 0.0f);
        mf[tid] = sgn * powf(fabsf(macc), pe);
    }
    __syncthreads();

    // FC: one thread per output row; two accumulators for ILP
    {
        const float4* __restrict__ Wr = (const float4*)(W + (size_t)tid * 256);
        const float4* __restrict__ mv = (const float4*)mf;
        float a0 = 0.f, a1 = 0.f;
#pragma unroll
        for (int k4 = 0; k4 < 64; k4 += 2) {
            const float4 w0 = Wr[k4],     m0 = mv[k4];
            const float4 w1 = Wr[k4 + 1], m1 = mv[k4 + 1];
            a0 = fmaf(w0.x, m0.x, a0); a0 = fmaf(w0.y, m0.y, a0);
            a0 = fmaf(w0.z, m0.z, a0); a0 = fmaf(w0.w, m0.w, a0);
            a1 = fmaf(w1.x, m1.x, a1); a1 = fmaf(w1.y, m1.y, a1);
            a1 = fmaf(w1.z, m1.z, a1); a1 = fmaf(w1.w, m1.w, a1);
        }
        fvv[tid] = a0 + a1 + bias[tid];
    }
    __syncthreads();

    // L2 normalize
    {
        float sq = fvv[tid] * fvv[tid];
        sq += __shfl_xor_sync(0xFFFFFFFFu, sq, 16);
        sq += __shfl_xor_sync(0xFFFFFFFFu, sq, 8);
        sq += __shfl_xor_sync(0xFFFFFFFFu, sq, 4);
        sq += __shfl_xor_sync(0xFFFFFFFFu, sq, 2);
        sq += __shfl_xor_sync(0xFFFFFFFFu, sq, 1);
        if (l == 0) warpsum[w] = sq;
    }
    __syncthreads();
    if (tid == 0) {
        float ss = 0.f;
#pragma unroll
        for (int ww = 0; ww < 8; ww++) ss += warpsum[ww];
        s_nrm = fmaxf(sqrtf(ss), 1e-12f);
    }
    __syncthreads();
    out[(size_t)b2 * 256 + tid] = fvv[tid] / s_nrm;
}

// ---------------------------------------------------------------------------
// kernel_launch: x [64*16384*16] f32, W [256*256] f32, b [256] f32, p [1] f32.
// out: [64*256] f32.
// ---------------------------------------------------------------------------
extern "C" void kernel_launch(void* const* d_in, const int* in_sizes, int n_in,
                              void* d_out, int out_size) {
    const float* x    = (const float*)d_in[0];
    const float* W    = (const float*)d_in[1];
    const float* bias = (const float*)d_in[2];
    const float* p    = (const float*)d_in[3];
    float* out = (float*)d_out;

    soap_fused<<<GRID, T1>>>(x, W, bias, p, out);
}